// round 7
// baseline (speedup 1.0000x reference)
#include <cuda_runtime.h>
#include <cstdint>

// ============================================================================
// quan_Linear_fi: exact reproduction of JAX reference (PARTITIONABLE threefry).
//   B=2, S=128, IN=512, OUT=512, BITS=8 (weight quant), FI width=16, BER=1e-5
//
// random_bits (partitionable): bits[j] = o0^o1, (o0,o1)=threefry2x32(key,(0,j))
// bernoulli(1e-5): bits < 43008.  fold_in = raw cipher -> compile-time subkeys.
//
// R7 perf change vs R6 (values bit-identical):
//  - ALL integer adds in the cipher (round adds AND key injections) forced to
//    IMAD on the fma pipe via opaque `one` + immediate key constants.
//    ALU pipe (binding resource) drops from ~54 to ~43 ops/block.
// ============================================================================

#define HALF_N   (1u << 25)    // batch stride in logical p/c tensor [2,512,128,512]
#define NCHAIN   131072u       // 2*512*128 cumsum chains

__device__ float    g_wq[512 * 512];     // transposed: [k][o]
__device__ float    g_c[1u << 26];       // [k][chain], chain = b*65536+s*512+o
__device__ float    g_y[2 * 512 * 128];  // [b][s][o]
__device__ unsigned g_wmax, g_pmax, g_cmax, g_ymax, g_one;

// ---------------------------------------------------------------------------
// threefry2x32 (JAX-exact): compile-time version for subkey derivation
// ---------------------------------------------------------------------------
struct U2c { unsigned a, b; };

__host__ __device__ constexpr unsigned rotl_c(unsigned x, int d) {
    return (x << d) | (x >> (32 - d));
}

__host__ __device__ constexpr U2c tf_c(unsigned k0, unsigned k1,
                                       unsigned x0, unsigned x1) {
    unsigned ks2 = k0 ^ k1 ^ 0x1BD11BDAu;
    const int RA[4] = {13, 15, 26, 6};
    const int RB[4] = {17, 29, 16, 24};
    x0 += k0;  x1 += k1;
    for (int i = 0; i < 4; i++) { x0 += x1; x1 = rotl_c(x1, RA[i]); x1 ^= x0; }
    x0 += k1;  x1 += ks2 + 1u;
    for (int i = 0; i < 4; i++) { x0 += x1; x1 = rotl_c(x1, RB[i]); x1 ^= x0; }
    x0 += ks2; x1 += k0 + 2u;
    for (int i = 0; i < 4; i++) { x0 += x1; x1 = rotl_c(x1, RA[i]); x1 ^= x0; }
    x0 += k0;  x1 += k1 + 3u;
    for (int i = 0; i < 4; i++) { x0 += x1; x1 = rotl_c(x1, RB[i]); x1 ^= x0; }
    x0 += k1;  x1 += ks2 + 4u;
    for (int i = 0; i < 4; i++) { x0 += x1; x1 = rotl_c(x1, RA[i]); x1 ^= x0; }
    x0 += ks2; x1 += k0 + 5u;
    return U2c{x0, x1};
}

// subkey(stage s, bit b) = fold_in(fold_in(key(42), s), b); key(42) = (0, 42)
__host__ __device__ constexpr U2c subkey_c(int s, int b) {
    U2c ks = tf_c(0u, 42u, 0u, (unsigned)s);
    return tf_c(ks.a, ks.b, 0u, (unsigned)b);
}

// ---------------------------------------------------------------------------
// Runtime threefry block with EVERY add on the fma pipe:
//   round add:      x0 = x1 * one + x0            (IMAD, reg form)
//   key injection:  x  = one * IMM + x            (IMAD, immediate multiplier)
// `one` == 1 loaded from g_one; ptxas cannot fold it, so IMADs survive.
// ALU pipe keeps only SHF (rotates) + LOP3 (xors) + compare/mask.
// ---------------------------------------------------------------------------
#define TF_ADD(dst, src) \
    asm("mad.lo.u32 %0, %1, %2, %0;" : "+r"(dst) : "r"(src), "r"(one))
#define TF_INJ(reg, IMM) \
    asm("mad.lo.u32 %0, %1, %2, %0;" : "+r"(reg) : "r"(one), "n"(IMM))
#define TF_ROUND(r) { TF_ADD(x0, x1); \
    x1 = __funnelshift_l(x1, x1, (r)); x1 ^= x0; }

template <unsigned K0, unsigned K1>
__device__ __forceinline__ unsigned tf_fi(unsigned j, unsigned one) {
    constexpr unsigned KS2 = K0 ^ K1 ^ 0x1BD11BDAu;
    unsigned x0, x1;
    // x1 = j + K1 ; x0 = x1 + K0  (init + first round-add fused, both IMAD)
    asm("mad.lo.u32 %0, %1, %2, %3;" : "=r"(x1) : "r"(one), "n"(K1), "r"(j));
    asm("mad.lo.u32 %0, %1, %2, %3;" : "=r"(x0) : "r"(one), "n"(K0), "r"(x1));
    x1 = __funnelshift_l(x1, x1, 13); x1 ^= x0;
    TF_ROUND(15) TF_ROUND(26) TF_ROUND(6)
    TF_INJ(x0, K1);  TF_INJ(x1, KS2 + 1u);
    TF_ROUND(17) TF_ROUND(29) TF_ROUND(16) TF_ROUND(24)
    TF_INJ(x0, KS2); TF_INJ(x1, K0 + 2u);
    TF_ROUND(13) TF_ROUND(15) TF_ROUND(26) TF_ROUND(6)
    TF_INJ(x0, K0);  TF_INJ(x1, K1 + 3u);
    TF_ROUND(17) TF_ROUND(29) TF_ROUND(16) TF_ROUND(24)
    TF_INJ(x0, K1);  TF_INJ(x1, KS2 + 4u);
    TF_ROUND(13) TF_ROUND(15) TF_ROUND(26) TF_ROUND(6)
    TF_INJ(x0, KS2); TF_INJ(x1, K0 + 5u);
    return x0 ^ x1;
}

// Build 16-bit flip masks for 2 independent element indices (ILP x2).
template <int S, int Bit>
__device__ __forceinline__ void mask2f(unsigned j0, unsigned j1,
                                       unsigned& m0, unsigned& m1,
                                       unsigned one) {
    if constexpr (Bit < 16) {
        constexpr U2c K = subkey_c(S, Bit);
        if (tf_fi<K.a, K.b>(j0, one) < 43008u) m0 |= (1u << Bit);
        if (tf_fi<K.a, K.b>(j1, one) < 43008u) m1 |= (1u << Bit);
        mask2f<S, Bit + 1>(j0, j1, m0, m1, one);
    }
}

// _bitflip_fi forward: quantize to 16-bit offset-binary, XOR mask, dequantize.
__device__ __forceinline__ float fi_q(float t, float sc, unsigned mask) {
    float r = rintf(__fdiv_rn(t, sc));             // jnp.round: half-to-even
    r = fminf(fmaxf(r, -32768.0f), 32767.0f);      // clip(-(n+1), n)
    int q  = (int)r;
    int q2 = (int)(((unsigned)(q + 32768)) ^ mask) - 32768;
    return __fmul_rn((float)q2, sc);
}

__device__ __forceinline__ float load_scale(const unsigned& g) {
    float sc = __fdiv_rn(__uint_as_float(g), 32767.0f);
    if (!(sc > 0.0f)) sc = 1.0f;                   // where(scale>0, scale, 1)
    return sc;
}

// ---------------------------------------------------------------------------
__global__ void k_init() {
    g_wmax = 0; g_pmax = 0; g_cmax = 0; g_ymax = 0; g_one = 1u;
}

__global__ void k_wmax(const float* __restrict__ w, int n) {
    float m = 0.0f;
    for (int i = blockIdx.x * blockDim.x + threadIdx.x; i < n;
         i += gridDim.x * blockDim.x)
        m = fmaxf(m, fabsf(w[i]));
    #pragma unroll
    for (int off = 16; off; off >>= 1)
        m = fmaxf(m, __shfl_xor_sync(0xffffffffu, m, off));
    if ((threadIdx.x & 31) == 0) atomicMax(&g_wmax, __float_as_uint(m));
}

// One block per input-feature k. Quantizes w column into TRANSPOSED g_wq[k][o];
// pmax = max_k( max_{b,s}|x[.,.,k]| * max_o|wq[o,k]| ) — exact for max|x*wq|.
__global__ void k_wq(const float* __restrict__ w, const float* __restrict__ x) {
    const int k = blockIdx.x;        // 0..511
    const int t = threadIdx.x;       // 0..255
    const float step = __fdiv_rn(__uint_as_float(g_wmax), 127.0f);
    float lmw = 0.0f;
    for (int o = t; o < 512; o += 256) {
        float wv = w[o * 512 + k];
        float r  = rintf(__fdiv_rn(wv, step));
        r = fminf(fmaxf(r, -128.0f), 127.0f);
        float wq = __fmul_rn(r, step);
        g_wq[k * 512 + o] = wq;                  // transposed, coalesced store
        lmw = fmaxf(lmw, fabsf(wq));
    }
    float lmx = fabsf(x[t * 512 + k]);   // t enumerates (b*128+s), 256 values
    __shared__ float smw[256], smx[256];
    smw[t] = lmw; smx[t] = lmx;
    __syncthreads();
    for (int off = 128; off; off >>= 1) {
        if (t < off) {
            smw[t] = fmaxf(smw[t], smw[t + off]);
            smx[t] = fmaxf(smx[t], smx[t + off]);
        }
        __syncthreads();
    }
    if (t == 0)
        atomicMax(&g_pmax, __float_as_uint(__fmul_rn(smx[0], smw[0])));
}

// Stage 0: p = x*wq -> bitflip_fi(0) -> cumsum over k -> g_c ; reduce cmax.
// One thread per (b,s,o): tid = b*65536 + s*512 + o (lanes vary o).
//   x loads warp-uniform, g_wq / g_c fully coalesced.
// Logical p-index: j = b*HALF_N + o*65536 + s*512 + k.
__global__ void __launch_bounds__(256) k_stage0(const float* __restrict__ x) {
    const unsigned tid = blockIdx.x * 256u + threadIdx.x;   // < 131072
    const unsigned o = tid & 511u, s = (tid >> 9) & 127u, b = tid >> 16;
    const unsigned one = g_one;
    const float sp = load_scale(g_pmax);
    const float* __restrict__ xp = x + (b * 128u + s) * 512u;
    const unsigned jb = b * HALF_N + o * 65536u + s * 512u;
    float c = 0.0f, cm = 0.0f;
    for (int k = 0; k < 512; k += 2) {
        unsigned m0 = 0, m1 = 0;
        mask2f<0, 0>(jb + k, jb + k + 1u, m0, m1, one);
        float2 xv = *(const float2*)(xp + k);               // uniform
        float w0 = g_wq[k * 512 + o];
        float w1 = g_wq[(k + 1) * 512 + o];
        float p0 = __fmul_rn(xv.x, w0);
        float p1 = __fmul_rn(xv.y, w1);
        c = __fadd_rn(c, fi_q(p0, sp, m0));
        g_c[(unsigned)k * NCHAIN + tid] = c;
        cm = fmaxf(cm, fabsf(c));
        c = __fadd_rn(c, fi_q(p1, sp, m1));
        g_c[(unsigned)(k + 1) * NCHAIN + tid] = c;
        cm = fmaxf(cm, fabsf(c));
    }
    #pragma unroll
    for (int off = 16; off; off >>= 1)
        cm = fmaxf(cm, __shfl_xor_sync(0xffffffffu, cm, off));
    if ((threadIdx.x & 31) == 0) atomicMax(&g_cmax, __float_as_uint(cm));
}

// Stage 1: c -> bitflip_fi(1); y = c_fi[511] + sum_{k=1..510}(c_fi[k]-c[k]).
// Same thread mapping as stage 0; stores y in [b][s][o] (= g_y[tid]).
__global__ void __launch_bounds__(256) k_stage1() {
    const unsigned tid = blockIdx.x * 256u + threadIdx.x;   // < 131072
    const unsigned o = tid & 511u, s = (tid >> 9) & 127u, b = tid >> 16;
    const unsigned one = g_one;
    const float sc = load_scale(g_cmax);
    const unsigned jb = b * HALF_N + o * 65536u + s * 512u;
    float a = 0.0f, y = 0.0f;
    for (int k = 0; k < 512; k += 2) {
        unsigned m0 = 0, m1 = 0;
        mask2f<1, 0>(jb + k, jb + k + 1u, m0, m1, one);
        float c0 = g_c[(unsigned)k * NCHAIN + tid];
        float c1 = g_c[(unsigned)(k + 1) * NCHAIN + tid];
        float f0 = fi_q(c0, sc, m0);
        float f1 = fi_q(c1, sc, m1);
        if (k > 0)                      // even slot interior (k = 2..510)
            a = __fadd_rn(a, __fsub_rn(f0, c0));
        if (k + 1 == 511)               // odd slot, last element: y_sum
            y = f1;
        else                            // odd slot interior (k+1 = 1..509)
            a = __fadd_rn(a, __fsub_rn(f1, c1));
    }
    y = __fadd_rn(y, a);                // y_sum + c_error
    g_y[tid] = y;                       // [b][s][o]
    float ym = fabsf(y);
    #pragma unroll
    for (int off = 16; off; off >>= 1)
        ym = fmaxf(ym, __shfl_xor_sync(0xffffffffu, ym, off));
    if ((threadIdx.x & 31) == 0) atomicMax(&g_ymax, __float_as_uint(ym));
}

// Stage 2: bitflip_fi(2) on logical y [2,512,128]; output [B,S,OUT] + bias.
// Thread t = s*512 + o handles both batches; logical j0 = o*128+s, j1 = j0+65536.
__global__ void k_stage2(const float* __restrict__ bias,
                         float* __restrict__ out) {
    const unsigned t = blockIdx.x * blockDim.x + threadIdx.x;    // < 65536
    const unsigned o = t & 511u, s = t >> 9;
    const unsigned one = g_one;
    const float sy = load_scale(g_ymax);
    const unsigned j0 = o * 128u + s;
    unsigned m0 = 0, m1 = 0;
    mask2f<2, 0>(j0, j0 + 65536u, m0, m1, one);
    float y0 = g_y[t];                  // [b=0][s][o]
    float y1 = g_y[t + 65536u];         // [b=1][s][o]
    float bv = bias[o];
    out[t]           = __fadd_rn(fi_q(y0, sy, m0), bv);
    out[t + 65536u]  = __fadd_rn(fi_q(y1, sy, m1), bv);
}

// ---------------------------------------------------------------------------
extern "C" void kernel_launch(void* const* d_in, const int* in_sizes, int n_in,
                              void* d_out, int out_size) {
    const float* x    = (const float*)d_in[0];   // [2,128,512]
    const float* w    = (const float*)d_in[1];   // [512,512]
    const float* bias = (const float*)d_in[2];   // [512]
    float* out = (float*)d_out;                  // [2,128,512]

    k_init<<<1, 1>>>();
    k_wmax<<<64, 256>>>(w, 512 * 512);
    k_wq<<<512, 256>>>(w, x);
    k_stage0<<<512, 256>>>(x);
    k_stage1<<<512, 256>>>();
    k_stage2<<<256, 256>>>(bias, out);
}

// round 8
// speedup vs baseline: 1.2124x; 1.2124x over previous
#include <cuda_runtime.h>
#include <cstdint>

// ============================================================================
// quan_Linear_fi: exact reproduction of JAX reference (PARTITIONABLE threefry).
//   B=2, S=128, IN=512, OUT=512, BITS=8 (weight quant), FI width=16, BER=1e-5
//
// random_bits (partitionable): bits[j] = o0^o1, (o0,o1)=threefry2x32(key,(0,j))
// bernoulli(1e-5): bits < 43008.  fold_in = raw cipher -> compile-time subkeys.
//
// R8 vs R6 (best): cipher reverted to R6 form; each 512-long cumsum chain is
// SPLIT in half across two threads (262144 threads: occ 36% -> ~86%, wave
// tail 86.5% -> 98.8%). Half-1 computes offset-free partial cumsum c';
// c = c' + S reconstructed on the fly (S = half-0 total). Adds ~1ulp
// re-association noise to rel_err (threshold 1e-3, previously 2.1e-4).
// ============================================================================

#define HALF_N   (1u << 25)    // batch stride in logical p/c tensor [2,512,128,512]
#define NCHAIN   131072u       // 2*512*128 cumsum chains
#define NTHR     262144u       // 2 threads per chain

__device__ float    g_wq[512 * 512];     // transposed: [k][o]
__device__ float    g_c[1u << 26];       // [k][chain]; half-1 planes hold c'
__device__ float    g_y[2 * 512 * 128];  // [b][s][o]
__device__ float    g_S[NCHAIN];         // half-0 cumsum totals
__device__ float    g_mn[NCHAIN], g_mx[NCHAIN];   // half-1 c' min/max
__device__ float    g_a0[NCHAIN], g_a1[NCHAIN], g_f511[NCHAIN];
__device__ unsigned g_wmax, g_pmax, g_cmax, g_ymax, g_one;

// ---------------------------------------------------------------------------
// threefry2x32 (JAX-exact): compile-time version for subkey derivation
// ---------------------------------------------------------------------------
struct U2c { unsigned a, b; };

__host__ __device__ constexpr unsigned rotl_c(unsigned x, int d) {
    return (x << d) | (x >> (32 - d));
}

__host__ __device__ constexpr U2c tf_c(unsigned k0, unsigned k1,
                                       unsigned x0, unsigned x1) {
    unsigned ks2 = k0 ^ k1 ^ 0x1BD11BDAu;
    const int RA[4] = {13, 15, 26, 6};
    const int RB[4] = {17, 29, 16, 24};
    x0 += k0;  x1 += k1;
    for (int i = 0; i < 4; i++) { x0 += x1; x1 = rotl_c(x1, RA[i]); x1 ^= x0; }
    x0 += k1;  x1 += ks2 + 1u;
    for (int i = 0; i < 4; i++) { x0 += x1; x1 = rotl_c(x1, RB[i]); x1 ^= x0; }
    x0 += ks2; x1 += k0 + 2u;
    for (int i = 0; i < 4; i++) { x0 += x1; x1 = rotl_c(x1, RA[i]); x1 ^= x0; }
    x0 += k0;  x1 += k1 + 3u;
    for (int i = 0; i < 4; i++) { x0 += x1; x1 = rotl_c(x1, RB[i]); x1 ^= x0; }
    x0 += k1;  x1 += ks2 + 4u;
    for (int i = 0; i < 4; i++) { x0 += x1; x1 = rotl_c(x1, RA[i]); x1 ^= x0; }
    x0 += ks2; x1 += k0 + 5u;
    return U2c{x0, x1};
}

// subkey(stage s, bit b) = fold_in(fold_in(key(42), s), b); key(42) = (0, 42)
__host__ __device__ constexpr U2c subkey_c(int s, int b) {
    U2c ks = tf_c(0u, 42u, 0u, (unsigned)s);
    return tf_c(ks.a, ks.b, 0u, (unsigned)b);
}

// ---------------------------------------------------------------------------
// Runtime threefry block (R6 form): round adds on fma pipe via opaque `one`;
// key injections stay as plain adds (IADD3).
// ---------------------------------------------------------------------------
#define TF_RND_F(r) {                                                         \
    asm("mad.lo.u32 %0, %1, %2, %0;" : "+r"(x0) : "r"(x1), "r"(one));         \
    x1 = __funnelshift_l(x1, x1, (r));                                        \
    x1 ^= x0; }

__device__ __forceinline__ unsigned tf_xor_f(unsigned k0, unsigned k1,
                                             unsigned x1, unsigned one) {
    unsigned ks2 = k0 ^ k1 ^ 0x1BD11BDAu;   // constant-folded per call site
    unsigned x0 = k0;                       // counts hi word (0) + k0
    x1 += k1;
    TF_RND_F(13) TF_RND_F(15) TF_RND_F(26) TF_RND_F(6)
    x0 += k1;  x1 += ks2 + 1u;
    TF_RND_F(17) TF_RND_F(29) TF_RND_F(16) TF_RND_F(24)
    x0 += ks2; x1 += k0 + 2u;
    TF_RND_F(13) TF_RND_F(15) TF_RND_F(26) TF_RND_F(6)
    x0 += k0;  x1 += k1 + 3u;
    TF_RND_F(17) TF_RND_F(29) TF_RND_F(16) TF_RND_F(24)
    x0 += k1;  x1 += ks2 + 4u;
    TF_RND_F(13) TF_RND_F(15) TF_RND_F(26) TF_RND_F(6)
    x0 += ks2; x1 += k0 + 5u;
    return x0 ^ x1;
}

// Build 16-bit flip masks for 2 independent element indices (ILP x2).
template <int S, int Bit>
__device__ __forceinline__ void mask2f(unsigned j0, unsigned j1,
                                       unsigned& m0, unsigned& m1,
                                       unsigned one) {
    if constexpr (Bit < 16) {
        constexpr U2c K = subkey_c(S, Bit);
        if (tf_xor_f(K.a, K.b, j0, one) < 43008u) m0 |= (1u << Bit);
        if (tf_xor_f(K.a, K.b, j1, one) < 43008u) m1 |= (1u << Bit);
        mask2f<S, Bit + 1>(j0, j1, m0, m1, one);
    }
}

// _bitflip_fi forward: quantize to 16-bit offset-binary, XOR mask, dequantize.
__device__ __forceinline__ float fi_q(float t, float sc, unsigned mask) {
    float r = rintf(__fdiv_rn(t, sc));             // jnp.round: half-to-even
    r = fminf(fmaxf(r, -32768.0f), 32767.0f);      // clip(-(n+1), n)
    int q  = (int)r;
    int q2 = (int)(((unsigned)(q + 32768)) ^ mask) - 32768;
    return __fmul_rn((float)q2, sc);
}

__device__ __forceinline__ float load_scale(const unsigned& g) {
    float sc = __fdiv_rn(__uint_as_float(g), 32767.0f);
    if (!(sc > 0.0f)) sc = 1.0f;                   // where(scale>0, scale, 1)
    return sc;
}

__device__ __forceinline__ void warp_amax(float v, unsigned* dst, int lane) {
    #pragma unroll
    for (int off = 16; off; off >>= 1)
        v = fmaxf(v, __shfl_xor_sync(0xffffffffu, v, off));
    if (lane == 0) atomicMax(dst, __float_as_uint(v));
}

// ---------------------------------------------------------------------------
__global__ void k_init() {
    g_wmax = 0; g_pmax = 0; g_cmax = 0; g_ymax = 0; g_one = 1u;
}

__global__ void k_wmax(const float* __restrict__ w, int n) {
    float m = 0.0f;
    for (int i = blockIdx.x * blockDim.x + threadIdx.x; i < n;
         i += gridDim.x * blockDim.x)
        m = fmaxf(m, fabsf(w[i]));
    warp_amax(m, &g_wmax, threadIdx.x & 31);
}

// One block per input-feature k. Quantizes w column into TRANSPOSED g_wq[k][o];
// pmax = max_k( max_{b,s}|x[.,.,k]| * max_o|wq[o,k]| ) — exact for max|x*wq|.
__global__ void k_wq(const float* __restrict__ w, const float* __restrict__ x) {
    const int k = blockIdx.x;        // 0..511
    const int t = threadIdx.x;       // 0..255
    const float step = __fdiv_rn(__uint_as_float(g_wmax), 127.0f);
    float lmw = 0.0f;
    for (int o = t; o < 512; o += 256) {
        float wv = w[o * 512 + k];
        float r  = rintf(__fdiv_rn(wv, step));
        r = fminf(fmaxf(r, -128.0f), 127.0f);
        float wq = __fmul_rn(r, step);
        g_wq[k * 512 + o] = wq;                  // transposed, coalesced store
        lmw = fmaxf(lmw, fabsf(wq));
    }
    float lmx = fabsf(x[t * 512 + k]);   // t enumerates (b*128+s), 256 values
    __shared__ float smw[256], smx[256];
    smw[t] = lmw; smx[t] = lmx;
    __syncthreads();
    for (int off = 128; off; off >>= 1) {
        if (t < off) {
            smw[t] = fmaxf(smw[t], smw[t + off]);
            smx[t] = fmaxf(smx[t], smx[t + off]);
        }
        __syncthreads();
    }
    if (t == 0)
        atomicMax(&g_pmax, __float_as_uint(__fmul_rn(smx[0], smw[0])));
}

// Stage 0: p = x*wq -> bitflip_fi(0) -> cumsum over k (split in half).
// tid < 262144: half = tid>>17, chain = tid & 131071 = b*65536 + s*512 + o.
// Half 0: true cumsum over k=0..255 -> g_c planes, total -> g_S, |c|max -> g_cmax.
// Half 1: offset-free partial cumsum c' over k=256..511 -> g_c planes; min/max
//         of c' -> g_mn/g_mx (cmax fixup happens in k_cmax with S).
// Logical p-index: j = b*HALF_N + o*65536 + s*512 + k.
__global__ void __launch_bounds__(256) k_stage0(const float* __restrict__ x) {
    const unsigned tid = blockIdx.x * 256u + threadIdx.x;   // < 262144
    const unsigned half = tid >> 17, chain = tid & (NCHAIN - 1u);
    const unsigned o = chain & 511u, s = (chain >> 9) & 127u, b = chain >> 16;
    const unsigned kb = half << 8;                          // 0 or 256
    const unsigned one = g_one;
    const float sp = load_scale(g_pmax);
    const float* __restrict__ xp = x + (b * 128u + s) * 512u + kb;
    const unsigned jb = b * HALF_N + o * 65536u + s * 512u + kb;
    float c = 0.0f, mn = 0.0f, mx = 0.0f;   // half0 uses mx as |c|max
    for (int i = 0; i < 256; i += 2) {
        const unsigned k = kb + i;
        unsigned m0 = 0, m1 = 0;
        mask2f<0, 0>(jb + i, jb + i + 1u, m0, m1, one);
        float2 xv = *(const float2*)(xp + i);               // warp-uniform
        float w0 = g_wq[k * 512 + o];
        float w1 = g_wq[(k + 1) * 512 + o];
        c = __fadd_rn(c, fi_q(__fmul_rn(xv.x, w0), sp, m0));
        g_c[k * NCHAIN + chain] = c;
        mn = fminf(mn, c); mx = fmaxf(mx, c);
        c = __fadd_rn(c, fi_q(__fmul_rn(xv.y, w1), sp, m1));
        g_c[(k + 1) * NCHAIN + chain] = c;
        mn = fminf(mn, c); mx = fmaxf(mx, c);
    }
    if (half == 0) {                        // uniform branch (block granular)
        g_S[chain] = c;
        warp_amax(fmaxf(mx, -mn), &g_cmax, threadIdx.x & 31);
    } else {
        g_mn[chain] = mn; g_mx[chain] = mx;
    }
}

// Fixup: fold half-0 totals into half-1 extrema -> complete g_cmax.
// max_k |c'[k]+S| = max(|mn+S|, |mx+S|) since +S preserves ordering.
__global__ void k_cmax() {
    const unsigned c = blockIdx.x * blockDim.x + threadIdx.x;    // < 131072
    const float S = g_S[c];
    float cm = fmaxf(fabsf(__fadd_rn(g_mn[c], S)),
                     fabsf(__fadd_rn(g_mx[c], S)));
    warp_amax(cm, &g_cmax, threadIdx.x & 31);
}

// Stage 1: c -> bitflip_fi(1); partials of c_error + f511 (split in half).
// Half 1 reconstructs c = c' + S on the fly.
__global__ void __launch_bounds__(256) k_stage1() {
    const unsigned tid = blockIdx.x * 256u + threadIdx.x;   // < 262144
    const unsigned half = tid >> 17, chain = tid & (NCHAIN - 1u);
    const unsigned o = chain & 511u, s = (chain >> 9) & 127u, b = chain >> 16;
    const unsigned kb = half << 8;
    const unsigned one = g_one;
    const float sc = load_scale(g_cmax);
    const float S = half ? g_S[chain] : 0.0f;
    const unsigned jb = b * HALF_N + o * 65536u + s * 512u + kb;
    float a = 0.0f, f511 = 0.0f;
    for (int i = 0; i < 256; i += 2) {
        const unsigned k = kb + i;
        unsigned m0 = 0, m1 = 0;
        mask2f<1, 0>(jb + i, jb + i + 1u, m0, m1, one);
        float c0 = g_c[k * NCHAIN + chain];
        float c1 = g_c[(k + 1) * NCHAIN + chain];
        if (half) { c0 = __fadd_rn(c0, S); c1 = __fadd_rn(c1, S); }
        float f0 = fi_q(c0, sc, m0);
        float f1 = fi_q(c1, sc, m1);
        if (k > 0)                      // even slot interior (k = 2..510)
            a = __fadd_rn(a, __fsub_rn(f0, c0));
        if (k + 1 == 511)               // odd slot, last element: y_sum
            f511 = f1;
        else                            // odd slot interior (k+1 = 1..509)
            a = __fadd_rn(a, __fsub_rn(f1, c1));
    }
    if (half == 0) g_a0[chain] = a;
    else          { g_a1[chain] = a; g_f511[chain] = f511; }
}

// Combine stage-1 partials: y = f511 + (a0 + a1); layout [b][s][o] = chain.
__global__ void k_yfix() {
    const unsigned c = blockIdx.x * blockDim.x + threadIdx.x;    // < 131072
    float y = __fadd_rn(g_f511[c], __fadd_rn(g_a0[c], g_a1[c]));
    g_y[c] = y;
    warp_amax(fabsf(y), &g_ymax, threadIdx.x & 31);
}

// Stage 2: bitflip_fi(2) on logical y [2,512,128]; output [B,S,OUT] + bias.
// Thread t = s*512 + o handles both batches; logical j0 = o*128+s, j1 = j0+65536.
__global__ void k_stage2(const float* __restrict__ bias,
                         float* __restrict__ out) {
    const unsigned t = blockIdx.x * blockDim.x + threadIdx.x;    // < 65536
    const unsigned o = t & 511u, s = t >> 9;
    const unsigned one = g_one;
    const float sy = load_scale(g_ymax);
    const unsigned j0 = o * 128u + s;
    unsigned m0 = 0, m1 = 0;
    mask2f<2, 0>(j0, j0 + 65536u, m0, m1, one);
    float y0 = g_y[t];                  // [b=0][s][o]
    float y1 = g_y[t + 65536u];         // [b=1][s][o]
    float bv = bias[o];
    out[t]           = __fadd_rn(fi_q(y0, sy, m0), bv);
    out[t + 65536u]  = __fadd_rn(fi_q(y1, sy, m1), bv);
}

// ---------------------------------------------------------------------------
extern "C" void kernel_launch(void* const* d_in, const int* in_sizes, int n_in,
                              void* d_out, int out_size) {
    const float* x    = (const float*)d_in[0];   // [2,128,512]
    const float* w    = (const float*)d_in[1];   // [512,512]
    const float* bias = (const float*)d_in[2];   // [512]
    float* out = (float*)d_out;                  // [2,128,512]

    k_init<<<1, 1>>>();
    k_wmax<<<64, 256>>>(w, 512 * 512);
    k_wq<<<512, 256>>>(w, x);
    k_stage0<<<1024, 256>>>(x);
    k_cmax<<<512, 256>>>();
    k_stage1<<<1024, 256>>>();
    k_yfix<<<512, 256>>>();
    k_stage2<<<256, 256>>>(bias, out);
}